// round 12
// baseline (speedup 1.0000x reference)
#include <cuda_runtime.h>
#include <math.h>

#define N_ATOMS 2048
#define HID     32
#define CUTOFF  2.5f
#define CUTOFF2 6.25f
#define JCHUNK  32
#define LUT_B   512           // smem LUT bins over d in [0, CUTOFF]; +1 guard
#define NDIAG   64            // 8 diagonal tiles x 8 chunks, weight 0.5
#define NBLK    288           // 64 diag + 224 off-diag

__device__ double   g_energy = 0.0;
__device__ unsigned g_done   = 0;

// cumulative off-diagonal chunk counts per i-tile (count ti = (7-ti)*8)
__constant__ int c_off[9] = {0, 56, 104, 144, 176, 200, 216, 224, 224};

__device__ __forceinline__ float tanh_fast(float x) {
    float y;
    asm("tanh.approx.f32 %0, %1;" : "=f"(y) : "f"(x));
    return y;
}
__device__ __forceinline__ float sqrt_fast(float x) {
    float y;
    asm("sqrt.approx.f32 %0, %1;" : "=f"(y) : "f"(x));
    return y;
}

__global__ __launch_bounds__(256, 4) void pair_kernel(
    const float* __restrict__ xyz,
    const float* __restrict__ cell,
    const float* __restrict__ W1,
    const float* __restrict__ b1,
    const float* __restrict__ W2,
    const float* __restrict__ b2,
    float* __restrict__ out)
{
    __shared__ float  sf[LUT_B + 1];      // f at bin edges
    __shared__ float2 slut[LUT_B + 1];    // (f, df) per bin + guard
    __shared__ float4 sj[JCHUNK];
    __shared__ float  swarp[8];

    const int tid = threadIdx.x;
    const int blk = blockIdx.x;

    // ---- block -> (i_tile, j0, weight) -------------------------------
    int   ti, j0;
    float w;
    if (blk < NDIAG) {                    // diagonal band: 256x32, w=0.5
        ti = blk >> 3;
        j0 = ti * 256 + (blk & 7) * JCHUNK;
        w  = 0.5f;
    } else {                              // strictly above diagonal, w=1
        int b = blk - NDIAG;
        ti = 0;
        #pragma unroll
        for (int k = 0; k < 7; k++)
            if (b >= c_off[k + 1]) ti = k + 1;
        j0 = (ti + 1) * 256 + (b - c_off[ti]) * JCHUNK;
        w  = 1.0f;
    }
    const int i = ti * 256 + tid;

    // ---- Phase 1: build private smem LUT of f(d) ---------------------
    {
        const float dd  = CUTOFF / (float)LUT_B;
        const float bb2 = b2[0];
        for (int p = tid; p <= LUT_B; p += 256) {
            float x = (float)p * dd;
            float f = bb2;
            #pragma unroll
            for (int k = 0; k < HID; k++)
                f = fmaf(tanh_fast(fmaf(x, W1[k], b1[k])), W2[k], f);
            sf[p] = f;
        }
    }
    // stage j-chunk concurrently
    if (tid < JCHUNK) {
        int j = j0 + tid;
        sj[tid] = make_float4(xyz[3*j], xyz[3*j+1], xyz[3*j+2], 0.f);
    }
    __syncthreads();

    for (int b = tid; b < LUT_B; b += 256)
        slut[b] = make_float2(sf[b], sf[b + 1] - sf[b]);
    if (tid == 0)
        slut[LUT_B] = make_float2(0.f, 0.f);   // guard: misses add 0
    __syncthreads();

    // ---- Phase 2: pair loop ------------------------------------------
    const float Lx = cell[0], Ly = cell[1], Lz = cell[2];
    const float xi = xyz[3*i], yi = xyz[3*i+1], zi = xyz[3*i+2];
    const float dscale = (float)LUT_B / CUTOFF;   // d -> bin
    const float tmax   = (float)LUT_B;            // guard bin

    float acc = 0.0f;

    #pragma unroll
    for (int jj = 0; jj < JCHUNK; jj++) {
        float4 p = sj[jj];
        float ax = fabsf(p.x - xi);
        float ay = fabsf(p.y - yi);
        float az = fabsf(p.z - zi);
        float wx = fminf(ax, Lx - ax);
        float wy = fminf(ay, Ly - ay);
        float wz = fminf(az, Lz - az);
        float dsq = fmaf(wx, wx, fmaf(wy, wy, wz * wz));

        float d  = sqrt_fast(dsq);
        float t  = fminf(d * dscale, tmax);    // miss -> guard bin
        int   it = (int)t;
        float fr = t - (float)it;
        float2 e = slut[it];                   // LDS.64
        acc += fmaf(fr, e.y, e.x);             // unconditional
    }

    // self-pair (d=0 -> bin 0 contributes f(0)), once per atom in diag chunk
    if ((unsigned)(i - j0) < (unsigned)JCHUNK)
        acc -= sf[0];

    acc *= w;

    // ---- Reduce + finish ---------------------------------------------
    #pragma unroll
    for (int off = 16; off > 0; off >>= 1)
        acc += __shfl_down_sync(0xFFFFFFFFu, acc, off);

    const int lane = tid & 31;
    const int warp = tid >> 5;
    if (lane == 0) swarp[warp] = acc;
    __syncthreads();

    if (warp == 0) {
        float v = (lane < 8) ? swarp[lane] : 0.0f;
        #pragma unroll
        for (int off = 4; off > 0; off >>= 1)
            v += __shfl_down_sync(0xFFFFFFFFu, v, off);
        if (lane == 0) {
            atomicAdd(&g_energy, (double)v);
            __threadfence();
            unsigned old = atomicAdd(&g_done, 1u);
            if (old == NBLK - 1) {
                __threadfence();
                double esum = __longlong_as_double(
                    atomicExch((unsigned long long*)&g_energy, 0ULL));
                out[0] = (float)esum;          // triangle: no halving
                __threadfence();
                atomicExch(&g_done, 0u);
            }
        }
    }
}

extern "C" void kernel_launch(void* const* d_in, const int* in_sizes, int n_in,
                              void* d_out, int out_size)
{
    const float* xyz  = (const float*)d_in[0];
    const float* cell = (const float*)d_in[1];
    const float* W1   = (const float*)d_in[2];
    const float* b1   = (const float*)d_in[3];
    const float* W2   = (const float*)d_in[4];
    const float* b2   = (const float*)d_in[5];
    float* out = (float*)d_out;

    pair_kernel<<<NBLK, 256>>>(xyz, cell, W1, b1, W2, b2, out);
}

// round 13
// speedup vs baseline: 1.3200x; 1.3200x over previous
#include <cuda_runtime.h>
#include <math.h>

#define N_ATOMS 2048
#define HID     32
#define CUTOFF2 6.25f
#define JCHUNK  8
#define LUT_N   16384         // nearest-bin LUT over dsq in [0, CUTOFF2]; +1 guard
#define NDIAG   256           // 8 diagonal tiles x 32 chunks, weight 0.5
#define NBLK    1152          // 256 diag + 896 off-diag

__device__ double   g_energy = 0.0;
__device__ unsigned g_done   = 0;
__device__ float    g_lut[LUT_N + 1];

// cumulative off-diagonal chunk counts per i-tile (count ti = (7-ti)*32)
__constant__ int c_off[9] = {0, 224, 416, 576, 704, 800, 864, 896, 896};

__device__ __forceinline__ float tanh_fast(float x) {
    float y;
    asm("tanh.approx.f32 %0, %1;" : "=f"(y) : "f"(x));
    return y;
}
__device__ __forceinline__ float sqrt_fast(float x) {
    float y;
    asm("sqrt.approx.f32 %0, %1;" : "=f"(y) : "f"(x));
    return y;
}

// Nearest-bin LUT over s = dsq: entry i = f(sqrt(s_i)). Guard entry = 0.
__global__ __launch_bounds__(256) void lut_kernel(
    const float* __restrict__ W1, const float* __restrict__ b1,
    const float* __restrict__ W2, const float* __restrict__ b2)
{
    const int idx = blockIdx.x * blockDim.x + threadIdx.x;
    if (idx <= LUT_N) {
        if (idx == LUT_N) {
            g_lut[idx] = 0.0f;
        } else {
            const float ds = CUTOFF2 / (float)LUT_N;
            const float d0 = sqrt_fast((float)idx * ds);
            float f0 = b2[0];
            #pragma unroll
            for (int k = 0; k < HID; k++)
                f0 = fmaf(tanh_fast(fmaf(d0, W1[k], b1[k])), W2[k], f0);
            g_lut[idx] = f0;
        }
    }
    __threadfence();
    cudaTriggerProgrammaticLaunchCompletion();
}

__global__ __launch_bounds__(256, 6) void pair_kernel(
    const float* __restrict__ xyz,
    const float* __restrict__ cell,
    float* __restrict__ out)
{
    __shared__ float4 sj[JCHUNK];
    __shared__ float  swarp[8];

    const int tid = threadIdx.x;
    const int blk = blockIdx.x;

    // ---- block -> (i_tile, j0, weight) -------------------------------
    int   ti, j0;
    float w;
    if (blk < NDIAG) {                    // diagonal band: full 256x8, w=0.5
        ti = blk >> 5;
        j0 = ti * 256 + (blk & 31) * JCHUNK;
        w  = 0.5f;
    } else {                              // strictly above the diagonal, w=1
        int b = blk - NDIAG;
        ti = 0;
        #pragma unroll
        for (int k = 0; k < 7; k++)
            if (b >= c_off[k + 1]) ti = k + 1;
        j0 = (ti + 1) * 256 + (b - c_off[ti]) * JCHUNK;
        w  = 1.0f;
    }
    const int i = ti * 256 + tid;

    // Prologue: runs concurrently with lut_kernel (no g_lut dependence).
    if (tid < JCHUNK) {
        int j = j0 + tid;
        sj[tid] = make_float4(xyz[3*j], xyz[3*j+1], xyz[3*j+2], 0.f);
    }
    const float Lx = cell[0], Ly = cell[1], Lz = cell[2];
    const float xi = xyz[3*i], yi = xyz[3*i+1], zi = xyz[3*i+2];
    __syncthreads();

    // Gate on lut_kernel's triggered completion before any g_lut read.
    cudaGridDependencySynchronize();

    const float sscale = (float)LUT_N / CUTOFF2;   // dsq -> bin
    const float tmax   = (float)LUT_N;             // guard bin (value 0)

    float acc = 0.0f;

    #pragma unroll
    for (int jj = 0; jj < JCHUNK; jj++) {
        float4 p = sj[jj];
        // MIC magnitude per dim: |dx_mic| = min(|dx|, L - |dx|)  (|dx| < L)
        float ax = fabsf(p.x - xi);
        float ay = fabsf(p.y - yi);
        float az = fabsf(p.z - zi);
        float wx = fminf(ax, Lx - ax);
        float wy = fminf(ay, Ly - ay);
        float wz = fminf(az, Lz - az);
        float dsq = fmaf(wx, wx, fmaf(wy, wy, wz * wz));

        float t  = fminf(dsq * sscale, tmax);      // miss -> guard bin (0)
        int   it = __float2int_rn(t);              // nearest bin
        acc += __ldg(&g_lut[it]);                  // unconditional
    }

    // self-pair (dsq = 0 -> bin 0 = f(0)) appears once per atom, in its diag chunk
    if ((unsigned)(i - j0) < (unsigned)JCHUNK)
        acc -= __ldg(&g_lut[0]);

    acc *= w;

    // warp reduce in float
    #pragma unroll
    for (int off = 16; off > 0; off >>= 1)
        acc += __shfl_down_sync(0xFFFFFFFFu, acc, off);

    const int lane = tid & 31;
    const int warp = tid >> 5;
    if (lane == 0) swarp[warp] = acc;
    __syncthreads();

    if (warp == 0) {
        float v = (lane < 8) ? swarp[lane] : 0.0f;
        #pragma unroll
        for (int off = 4; off > 0; off >>= 1)
            v += __shfl_down_sync(0xFFFFFFFFu, v, off);
        if (lane == 0) {
            atomicAdd(&g_energy, (double)v);
            __threadfence();
            unsigned old = atomicAdd(&g_done, 1u);
            if (old == NBLK - 1) {
                __threadfence();
                double esum = __longlong_as_double(
                    atomicExch((unsigned long long*)&g_energy, 0ULL));
                out[0] = (float)esum;          // triangle: no halving
                __threadfence();
                atomicExch(&g_done, 0u);
            }
        }
    }
}

extern "C" void kernel_launch(void* const* d_in, const int* in_sizes, int n_in,
                              void* d_out, int out_size)
{
    const float* xyz  = (const float*)d_in[0];
    const float* cell = (const float*)d_in[1];
    const float* W1   = (const float*)d_in[2];
    const float* b1   = (const float*)d_in[3];
    const float* W2   = (const float*)d_in[4];
    const float* b2   = (const float*)d_in[5];
    float* out = (float*)d_out;

    lut_kernel<<<(LUT_N + 1 + 255) / 256, 256>>>(W1, b1, W2, b2);

    // PDL: pair_kernel pre-launches while lut_kernel runs; CTAs block at
    // cudaGridDependencySynchronize() until lut triggers completion.
    cudaLaunchConfig_t cfg = {};
    cfg.gridDim  = dim3(NBLK, 1, 1);
    cfg.blockDim = dim3(256, 1, 1);
    cfg.dynamicSmemBytes = 0;
    cfg.stream = 0;
    cudaLaunchAttribute attr[1];
    attr[0].id = cudaLaunchAttributeProgrammaticStreamSerialization;
    attr[0].val.programmaticStreamSerializationAllowed = 1;
    cfg.attrs = attr;
    cfg.numAttrs = 1;
    cudaLaunchKernelEx(&cfg, pair_kernel, xyz, cell, out);
}